// round 1
// baseline (speedup 1.0000x reference)
#include <cuda_runtime.h>
#include <math.h>

#define S_LEN 2048
#define HID   2048
#define NH    16
#define NKV   4
#define HD    128
#define BATCH 2

// Scratch buffers (allocation-free rule: __device__ globals)
__device__ float g_q[(size_t)BATCH * NH  * S_LEN * HD];   // [b][h][s][d]
__device__ float g_k[(size_t)BATCH * NKV * S_LEN * HD];   // [b][kh][s][d]
__device__ float g_v[(size_t)BATCH * NKV * S_LEN * HD];   // [b][kh][s][d]
__device__ float g_ao[(size_t)BATCH * S_LEN * HID];       // [b][s][h*128+d]

// ---------------------------------------------------------------------------
// Tiled fp32 GEMM mainloop: C[m][n] = sum_k A[m][k] * B[n][k]  (both K-major)
// BM=128, BN=64, BK=16, 256 threads, 8x4 per-thread tile.
// ---------------------------------------------------------------------------
#define GBM 128
#define GBN 64
#define GBK 16

__device__ __forceinline__ void gemm_mainloop(const float* __restrict__ A,
                                              const float* __restrict__ B,
                                              int m0, int n0, float acc[8][4])
{
    __shared__ float As[GBK][GBM];
    __shared__ float Bs[GBK][GBN];

    int tid = threadIdx.x;
    int ty = tid >> 4;            // 0..15 : 8 rows each
    int tx = tid & 15;            // 0..15 : 4 cols each
    int ar = tid >> 1;            // 0..127
    int ac = (tid & 1) * 8;       // 0 or 8
    int br = tid >> 2;            // 0..63
    int bc = (tid & 3) * 4;       // 0,4,8,12

    const float* ap = A + (size_t)(m0 + ar) * HID + ac;
    const float* bp = B + (size_t)(n0 + br) * HID + bc;

#pragma unroll
    for (int i = 0; i < 8; i++)
#pragma unroll
        for (int j = 0; j < 4; j++) acc[i][j] = 0.f;

    for (int k0 = 0; k0 < HID; k0 += GBK) {
        float4 a0 = *(const float4*)ap;
        float4 a1 = *(const float4*)(ap + 4);
        float4 b0 = *(const float4*)bp;
        ap += GBK; bp += GBK;

        As[ac + 0][ar] = a0.x; As[ac + 1][ar] = a0.y;
        As[ac + 2][ar] = a0.z; As[ac + 3][ar] = a0.w;
        As[ac + 4][ar] = a1.x; As[ac + 5][ar] = a1.y;
        As[ac + 6][ar] = a1.z; As[ac + 7][ar] = a1.w;
        Bs[bc + 0][br] = b0.x; Bs[bc + 1][br] = b0.y;
        Bs[bc + 2][br] = b0.z; Bs[bc + 3][br] = b0.w;
        __syncthreads();

#pragma unroll
        for (int kk = 0; kk < GBK; kk++) {
            float4 av0 = *(const float4*)&As[kk][ty * 8];
            float4 av1 = *(const float4*)&As[kk][ty * 8 + 4];
            float4 bv  = *(const float4*)&Bs[kk][tx * 4];
            float a[8] = {av0.x, av0.y, av0.z, av0.w, av1.x, av1.y, av1.z, av1.w};
            float c[4] = {bv.x, bv.y, bv.z, bv.w};
#pragma unroll
            for (int i = 0; i < 8; i++)
#pragma unroll
                for (int j = 0; j < 4; j++)
                    acc[i][j] = fmaf(a[i], c[j], acc[i][j]);
        }
        __syncthreads();
    }
}

// ---------------------------------------------------------------------------
// Fused QKV projection: N = 2048 (Q) + 512 (K) + 512 (V) = 3072
// Scatters results into head-major layout.
// ---------------------------------------------------------------------------
__global__ void __launch_bounds__(256) gemm_qkv(const float* __restrict__ x,
                                                const float* __restrict__ wq,
                                                const float* __restrict__ wk,
                                                const float* __restrict__ wv)
{
    int n0 = blockIdx.x * GBN;
    int m0 = blockIdx.y * GBM;

    const float* B; int nbase, kind;
    if (n0 < NH * HD)               { B = wq; nbase = n0;               kind = 0; }
    else if (n0 < (NH + NKV) * HD)  { B = wk; nbase = n0 - NH * HD;     kind = 1; }
    else                            { B = wv; nbase = n0 - (NH+NKV)*HD; kind = 2; }

    float acc[8][4];
    gemm_mainloop(x, B, m0, nbase, acc);

    int tid = threadIdx.x, ty = tid >> 4, tx = tid & 15;
    int n = nbase + tx * 4;
    int h = n >> 7, d = n & 127;

#pragma unroll
    for (int i = 0; i < 8; i++) {
        int m = m0 + ty * 8 + i;
        int b = m >> 11, s = m & (S_LEN - 1);
        float4 v = make_float4(acc[i][0], acc[i][1], acc[i][2], acc[i][3]);
        if (kind == 0)
            *(float4*)&g_q[((size_t)(b * NH + h) * S_LEN + s) * HD + d] = v;
        else if (kind == 1)
            *(float4*)&g_k[((size_t)(b * NKV + h) * S_LEN + s) * HD + d] = v;
        else
            *(float4*)&g_v[((size_t)(b * NKV + h) * S_LEN + s) * HD + d] = v;
    }
}

// ---------------------------------------------------------------------------
// Output projection: out = g_ao @ wo^T
// ---------------------------------------------------------------------------
__global__ void __launch_bounds__(256) gemm_wo(const float* __restrict__ wo,
                                               float* __restrict__ out)
{
    int n0 = blockIdx.x * GBN;
    int m0 = blockIdx.y * GBM;
    float acc[8][4];
    gemm_mainloop(g_ao, wo, m0, n0, acc);

    int tid = threadIdx.x, ty = tid >> 4, tx = tid & 15;
#pragma unroll
    for (int i = 0; i < 8; i++) {
        int m = m0 + ty * 8 + i;
        *(float4*)&out[(size_t)m * HID + n0 + tx * 4] =
            make_float4(acc[i][0], acc[i][1], acc[i][2], acc[i][3]);
    }
}

// ---------------------------------------------------------------------------
// RoPE (in place). 64 threads = one row; thread d handles the (d, d+64) pair.
// inv_freq computed in double to match jnp's fp32 pow to within its own ULP,
// then the angle multiply is done in fp32 exactly like the reference.
// ---------------------------------------------------------------------------
__device__ __forceinline__ void rope_row(float* base, int s)
{
    int d = threadIdx.x;                     // 0..63
    // log2(10000)/64 = 0.20762050593046747
    float inv = (float)exp2(-(double)d * 0.20762050593046747);
    float ang = (float)s * inv;
    float sn, cs;
    sincosf(ang, &sn, &cs);
    float x1 = base[d], x2 = base[d + 64];
    base[d]      = x1 * cs - x2 * sn;
    base[d + 64] = x1 * sn + x2 * cs;
}

__global__ void rope_q() { rope_row(g_q + (size_t)blockIdx.x * HD, blockIdx.x & (S_LEN - 1)); }
__global__ void rope_k() { rope_row(g_k + (size_t)blockIdx.x * HD, blockIdx.x & (S_LEN - 1)); }

// ---------------------------------------------------------------------------
// Flash-style causal attention, fp32. BM=BN=64, 256 threads.
// key_weights[h] * D^-0.5 folded into Q at load time.
// Smem strides padded (68 / 132) for conflict-free LDS.128.
// ---------------------------------------------------------------------------
#define AQK 68    // padded stride (64 -> 68) for Qs/Ks (d-major) and Ps rows
#define AVS 132   // padded stride (128 -> 132) for Vs rows
#define ATTN_SMEM_BYTES ((128 * AQK * 2 + 64 * AVS + 64 * AQK + 192) * 4)

__global__ void __launch_bounds__(256) attn_kernel(const float* __restrict__ kw)
{
    extern __shared__ float sm[];
    float* Qs = sm;                         // [128][AQK] : Qs[d*AQK + r]
    float* Ks = Qs + 128 * AQK;             // [128][AQK] : Ks[d*AQK + c]
    float* Vs = Ks + 128 * AQK;             // [64][AVS]  : Vs[j*AVS + d]
    float* Ps = Vs + 64 * AVS;              // [64][AQK]  : Ps[r*AQK + j]
    float* mS = Ps + 64 * AQK;
    float* lS = mS + 64;
    float* aS = lS + 64;

    int tid = threadIdx.x;
    int ty = tid >> 4, tx = tid & 15;       // 16x16, rows = ty*4.., cols = tx*4..
    int mt = blockIdx.x, h = blockIdx.y, b = blockIdx.z;
    int m0 = mt * 64;
    int kh = h >> 2;
    float scale = kw[h] * 0.08838834764831845f;   // key_weight * 128^-0.5

    const float* qg = g_q + ((size_t)(b * NH  + h ) * S_LEN + m0) * HD;
    const float* kg = g_k + ((size_t)(b * NKV + kh) * S_LEN) * HD;
    const float* vg = g_v + ((size_t)(b * NKV + kh) * S_LEN) * HD;

    int lr = tid >> 2;            // 0..63 (tile row for loads)
    int lc = (tid & 3) * 4;       // 0,4,8,12

    // Load Q tile transposed + scaled
    {
        const float* src = qg + (size_t)lr * HD;
#pragma unroll
        for (int q = 0; q < 8; q++) {
            int d = lc + q * 16;
            float4 v = *(const float4*)(src + d);
            Qs[(d + 0) * AQK + lr] = v.x * scale;
            Qs[(d + 1) * AQK + lr] = v.y * scale;
            Qs[(d + 2) * AQK + lr] = v.z * scale;
            Qs[(d + 3) * AQK + lr] = v.w * scale;
        }
    }
    if (tid < 64) { mS[tid] = -1e30f; lS[tid] = 0.f; }

    float o[4][8];
#pragma unroll
    for (int i = 0; i < 4; i++)
#pragma unroll
        for (int d = 0; d < 8; d++) o[i][d] = 0.f;

    for (int nt = 0; nt <= mt; nt++) {
        int n0 = nt * 64;
        __syncthreads();   // previous PV done (and first-iter Q/stat stores done)

        // Load K (transposed) and V tiles
        {
            const float* ks = kg + (size_t)(n0 + lr) * HD;
            const float* vs = vg + (size_t)(n0 + lr) * HD;
#pragma unroll
            for (int q = 0; q < 8; q++) {
                int d = lc + q * 16;
                float4 kv = *(const float4*)(ks + d);
                Ks[(d + 0) * AQK + lr] = kv.x;
                Ks[(d + 1) * AQK + lr] = kv.y;
                Ks[(d + 2) * AQK + lr] = kv.z;
                Ks[(d + 3) * AQK + lr] = kv.w;
                float4 vv = *(const float4*)(vs + d);
                *(float4*)&Vs[lr * AVS + d] = vv;
            }
        }
        __syncthreads();

        // S = (Q*scale) K^T, 4x4 per thread
        float sacc[4][4];
#pragma unroll
        for (int i = 0; i < 4; i++)
#pragma unroll
            for (int j = 0; j < 4; j++) sacc[i][j] = 0.f;

#pragma unroll 8
        for (int kk = 0; kk < HD; kk++) {
            float4 av = *(const float4*)&Qs[kk * AQK + ty * 4];
            float4 bv = *(const float4*)&Ks[kk * AQK + tx * 4];
            float a[4] = {av.x, av.y, av.z, av.w};
            float c[4] = {bv.x, bv.y, bv.z, bv.w};
#pragma unroll
            for (int i = 0; i < 4; i++)
#pragma unroll
                for (int j = 0; j < 4; j++)
                    sacc[i][j] = fmaf(a[i], c[j], sacc[i][j]);
        }

        if (nt == mt) {  // causal mask on the diagonal tile
#pragma unroll
            for (int i = 0; i < 4; i++)
#pragma unroll
                for (int j = 0; j < 4; j++)
                    if (n0 + tx * 4 + j > m0 + ty * 4 + i) sacc[i][j] = -1e30f;
        }
#pragma unroll
        for (int i = 0; i < 4; i++)
            *(float4*)&Ps[(ty * 4 + i) * AQK + tx * 4] =
                make_float4(sacc[i][0], sacc[i][1], sacc[i][2], sacc[i][3]);
        __syncthreads();

        // Online softmax: one thread per row
        if (tid < 64) {
            float* pr = &Ps[tid * AQK];
            float mold = mS[tid];
            float mx = mold;
#pragma unroll 8
            for (int j = 0; j < 64; j++) mx = fmaxf(mx, pr[j]);
            float alpha = __expf(mold - mx);
            float sum = 0.f;
#pragma unroll 8
            for (int j = 0; j < 64; j++) {
                float e = __expf(pr[j] - mx);
                pr[j] = e;
                sum += e;
            }
            mS[tid] = mx;
            lS[tid] = lS[tid] * alpha + sum;
            aS[tid] = alpha;
        }
        __syncthreads();

        // Rescale running O, then O += P @ V
#pragma unroll
        for (int i = 0; i < 4; i++) {
            float al = aS[ty * 4 + i];
#pragma unroll
            for (int d = 0; d < 8; d++) o[i][d] *= al;
        }
#pragma unroll 2
        for (int j = 0; j < 64; j++) {
            float4 v0 = *(const float4*)&Vs[j * AVS + tx * 8];
            float4 v1 = *(const float4*)&Vs[j * AVS + tx * 8 + 4];
#pragma unroll
            for (int i = 0; i < 4; i++) {
                float p = Ps[(ty * 4 + i) * AQK + j];
                o[i][0] = fmaf(p, v0.x, o[i][0]);
                o[i][1] = fmaf(p, v0.y, o[i][1]);
                o[i][2] = fmaf(p, v0.z, o[i][2]);
                o[i][3] = fmaf(p, v0.w, o[i][3]);
                o[i][4] = fmaf(p, v1.x, o[i][4]);
                o[i][5] = fmaf(p, v1.y, o[i][5]);
                o[i][6] = fmaf(p, v1.z, o[i][6]);
                o[i][7] = fmaf(p, v1.w, o[i][7]);
            }
        }
    }

    // Normalize and write to [b][s][h*128+d] layout for the WO GEMM
#pragma unroll
    for (int i = 0; i < 4; i++) {
        int r = ty * 4 + i;
        float inv = 1.0f / lS[r];
        float* dst = g_ao + ((size_t)(b * S_LEN + m0 + r)) * HID + h * HD + tx * 8;
        *(float4*)&dst[0] = make_float4(o[i][0] * inv, o[i][1] * inv,
                                        o[i][2] * inv, o[i][3] * inv);
        *(float4*)&dst[4] = make_float4(o[i][4] * inv, o[i][5] * inv,
                                        o[i][6] * inv, o[i][7] * inv);
    }
}

// ---------------------------------------------------------------------------
// Launch
// ---------------------------------------------------------------------------
extern "C" void kernel_launch(void* const* d_in, const int* in_sizes, int n_in,
                              void* d_out, int out_size)
{
    const float* x  = (const float*)d_in[0];
    const float* wq = (const float*)d_in[1];
    const float* wk = (const float*)d_in[2];
    const float* wv = (const float*)d_in[3];
    const float* wo = (const float*)d_in[4];
    const float* kw = (const float*)d_in[5];
    float* out = (float*)d_out;

    cudaFuncSetAttribute(attn_kernel,
                         cudaFuncAttributeMaxDynamicSharedMemorySize,
                         ATTN_SMEM_BYTES);

    // QKV projection: M=4096, N=3072
    gemm_qkv<<<dim3((NH + 2 * NKV) * HD / GBN, BATCH * S_LEN / GBM), 256>>>(x, wq, wk, wv);

    // RoPE
    rope_q<<<BATCH * NH  * S_LEN, 64>>>();
    rope_k<<<BATCH * NKV * S_LEN, 64>>>();

    // Attention
    attn_kernel<<<dim3(S_LEN / 64, NH, BATCH), 256, ATTN_SMEM_BYTES>>>(kw);

    // Output projection: M=4096, N=2048
    gemm_wo<<<dim3(HID / GBN, BATCH * S_LEN / GBM), 256>>>(wo, out);
}

// round 4
// speedup vs baseline: 1.3358x; 1.3358x over previous
#include <cuda_runtime.h>
#include <cuda_bf16.h>
#include <math.h>
#include <cstdint>

#define S_LEN 2048
#define HID   2048
#define NH    16
#define NKV   4
#define HD    128
#define BATCH 2

// Scratch buffers (allocation-free rule: __device__ globals)
__device__ float g_q[(size_t)BATCH * NH  * S_LEN * HD];   // [b][h][s][d]
__device__ float g_k[(size_t)BATCH * NKV * S_LEN * HD];   // [b][kh][s][d]
__device__ float g_v[(size_t)BATCH * NKV * S_LEN * HD];   // [b][kh][s][d]
__device__ float g_ao[(size_t)BATCH * S_LEN * HID];       // [b][s][h*128+d]

// ===========================================================================
// Warp-level MMA helpers (baseline PTX: sm_80+ features, no 'a' target needed)
// ===========================================================================
__device__ __forceinline__ uint32_t smem_u32(const void* p) {
    uint32_t a;
    asm("{ .reg .u64 t; cvta.to.shared.u64 t, %1; cvt.u32.u64 %0, t; }"
        : "=r"(a) : "l"(p));
    return a;
}

__device__ __forceinline__ void ldsm_x4(uint32_t r[4], uint32_t a) {
    asm volatile("ldmatrix.sync.aligned.m8n8.x4.shared.b16 {%0,%1,%2,%3}, [%4];"
                 : "=r"(r[0]), "=r"(r[1]), "=r"(r[2]), "=r"(r[3]) : "r"(a));
}
__device__ __forceinline__ void mma16816(float c[4], const uint32_t a[4],
                                         uint32_t b0, uint32_t b1) {
    asm volatile("mma.sync.aligned.m16n8k16.row.col.f32.bf16.bf16.f32 "
                 "{%0,%1,%2,%3}, {%4,%5,%6,%7}, {%8,%9}, {%0,%1,%2,%3};"
                 : "+f"(c[0]), "+f"(c[1]), "+f"(c[2]), "+f"(c[3])
                 : "r"(a[0]), "r"(a[1]), "r"(a[2]), "r"(a[3]), "r"(b0), "r"(b1));
}

// Split fp32 pair -> (hi bf16x2, lo bf16x2); hi = rn(x), lo = rn(x - hi).
__device__ __forceinline__ void split2(float x0, float x1, uint32_t& hi, uint32_t& lo) {
    asm("cvt.rn.bf16x2.f32 %0, %1, %2;" : "=r"(hi) : "f"(x1), "f"(x0));
    float h0 = __uint_as_float(hi << 16);
    float h1 = __uint_as_float(hi & 0xFFFF0000u);
    float l0 = x0 - h0;
    float l1 = x1 - h1;
    asm("cvt.rn.bf16x2.f32 %0, %1, %2;" : "=r"(lo) : "f"(l1), "f"(l0));
}

#define SWZ(o) ((o) ^ (((o) >> 3) & 0x70))

// ===========================================================================
// Split-bf16 tensor-core GEMM: C[128,128] tile of A[M,2048] * B[N,2048]^T
// BK=32 fp32 per chunk; smem per stage: A(128x64 bf16: hi|lo) + B same.
// 2 stages = 64KB. 8 warps (4x2), warp tile 32x64.
// ===========================================================================
#define BK 32
#define KCHUNKS (HID / BK)
#define TILE_BYTES 16384                // 128 rows x 128B
#define STAGE_BYTES (2 * TILE_BYTES)    // A + B
#define GEMM_SMEM_MMA (2 * STAGE_BYTES) // 64KB

__device__ __forceinline__ void gemm_mma_tile(const float* __restrict__ A,
                                              const float* __restrict__ B,
                                              int m0, int n0,
                                              float cacc[2][8][4], char* smem)
{
    int tid = threadIdx.x;
    int warp = tid >> 5, lane = tid & 31;
    int wm = warp & 3, wn = warp >> 2;

    int lrow = tid >> 1;           // 0..127
    int lk   = (tid & 1) * 16;     // 0 or 16

    const float* ap = A + (size_t)(m0 + lrow) * HID + lk;
    const float* bp = B + (size_t)(n0 + lrow) * HID + lk;

    uint32_t sbase = smem_u32(smem);

    // per-thread ldmatrix base offsets (within a tile)
    int lr16 = lane & 15;
    int lhalf = (lane >> 4) * 16;  // byte offset of 16B half along k

    float4 ra[4], rb[4];

#pragma unroll
    for (int mt = 0; mt < 2; mt++)
#pragma unroll
        for (int ng = 0; ng < 8; ng++)
#pragma unroll
            for (int i = 0; i < 4; i++) cacc[mt][ng][i] = 0.f;

    // ---- load chunk 0 ----
#pragma unroll
    for (int j = 0; j < 4; j++) {
        ra[j] = *(const float4*)(ap + j * 4);
        rb[j] = *(const float4*)(bp + j * 4);
    }

    auto store_stage = [&](int s) {
        char* ab = smem + s * STAGE_BYTES;
        char* bb = ab + TILE_BYTES;
#pragma unroll
        for (int j = 0; j < 4; j++) {
            uint32_t offh = (uint32_t)lrow * 128 + (lk + j * 4) * 2;
            uint32_t offl = offh + 64;
            uint32_t h0, l0, h1, l1;
            split2(ra[j].x, ra[j].y, h0, l0);
            split2(ra[j].z, ra[j].w, h1, l1);
            *(uint2*)(ab + SWZ(offh)) = make_uint2(h0, h1);
            *(uint2*)(ab + SWZ(offl)) = make_uint2(l0, l1);
            split2(rb[j].x, rb[j].y, h0, l0);
            split2(rb[j].z, rb[j].w, h1, l1);
            *(uint2*)(bb + SWZ(offh)) = make_uint2(h0, h1);
            *(uint2*)(bb + SWZ(offl)) = make_uint2(l0, l1);
        }
    };

    store_stage(0);
    __syncthreads();

    for (int c = 0; c < KCHUNKS; c++) {
        // prefetch next chunk into registers
        if (c + 1 < KCHUNKS) {
            const float* a2 = ap + (c + 1) * BK;
            const float* b2 = bp + (c + 1) * BK;
#pragma unroll
            for (int j = 0; j < 4; j++) {
                ra[j] = *(const float4*)(a2 + j * 4);
                rb[j] = *(const float4*)(b2 + j * 4);
            }
        }

        // compute on stage c&1
        uint32_t abase = sbase + (c & 1) * STAGE_BYTES;
        uint32_t bbase = abase + TILE_BYTES;

#pragma unroll
        for (int seg = 0; seg < 3; seg++) {
            int sa = (seg == 1) ? 64 : 0;   // A: hi, lo, hi
            int sb = (seg == 2) ? 64 : 0;   // B: hi, hi, lo
#pragma unroll
            for (int kk = 0; kk < 2; kk++) {
                uint32_t af[2][4];
#pragma unroll
                for (int mt = 0; mt < 2; mt++) {
                    uint32_t off = (uint32_t)(wm * 32 + mt * 16 + lr16) * 128
                                   + sa + kk * 32 + lhalf;
                    ldsm_x4(af[mt], abase + SWZ(off));
                }
                uint32_t b0[8], b1[8];
#pragma unroll
                for (int t = 0; t < 4; t++) {
                    uint32_t off = (uint32_t)(wn * 64 + t * 16 + lr16) * 128
                                   + sb + kk * 32 + lhalf;
                    uint32_t r[4];
                    ldsm_x4(r, bbase + SWZ(off));   // B is [n][k]: NON-trans load
                    b0[2 * t] = r[0]; b0[2 * t + 1] = r[1];
                    b1[2 * t] = r[2]; b1[2 * t + 1] = r[3];
                }
#pragma unroll
                for (int mt = 0; mt < 2; mt++)
#pragma unroll
                    for (int ng = 0; ng < 8; ng++)
                        mma16816(cacc[mt][ng], af[mt], b0[ng], b1[ng]);
            }
        }

        if (c + 1 < KCHUNKS) store_stage((c + 1) & 1);
        __syncthreads();
    }
}

// ---------------------------------------------------------------------------
// QKV projection: grid.x = 24 N-tiles (16 Q heads, 4 K heads, 4 V heads)
// ---------------------------------------------------------------------------
__global__ void __launch_bounds__(256, 1) gemm_qkv_mma(const float* __restrict__ x,
                                                       const float* __restrict__ wq,
                                                       const float* __restrict__ wk,
                                                       const float* __restrict__ wv)
{
    extern __shared__ char smem[];
    int nt = blockIdx.x;
    int m0 = blockIdx.y * 128;

    const float* B; float* dst_base; int h, nkvh;
    if (nt < 16)      { B = wq; h = nt;      dst_base = g_q; nkvh = NH;  }
    else if (nt < 20) { B = wk; h = nt - 16; dst_base = g_k; nkvh = NKV; }
    else              { B = wv; h = nt - 20; dst_base = g_v; nkvh = NKV; }

    float cacc[2][8][4];
    gemm_mma_tile(x, B, m0, h * HD, cacc, smem);

    int tid = threadIdx.x;
    int warp = tid >> 5, lane = tid & 31;
    int wm = warp & 3, wn = warp >> 2;
    int r0 = lane >> 2, c0 = (lane & 3) * 2;

#pragma unroll
    for (int mt = 0; mt < 2; mt++) {
#pragma unroll
        for (int ng = 0; ng < 8; ng++) {
            int col = wn * 64 + ng * 8 + c0;
#pragma unroll
            for (int half = 0; half < 2; half++) {
                int mg = m0 + wm * 32 + mt * 16 + r0 + half * 8;
                int b = mg >> 11, s = mg & (S_LEN - 1);
                float* d = dst_base + ((size_t)(b * nkvh + h) * S_LEN + s) * HD + col;
                *(float2*)d = make_float2(cacc[mt][ng][2 * half],
                                          cacc[mt][ng][2 * half + 1]);
            }
        }
    }
}

// ---------------------------------------------------------------------------
// Output projection: out = g_ao @ wo^T
// ---------------------------------------------------------------------------
__global__ void __launch_bounds__(256, 1) gemm_wo_mma(const float* __restrict__ wo,
                                                      float* __restrict__ out)
{
    extern __shared__ char smem[];
    int n0 = blockIdx.x * 128;
    int m0 = blockIdx.y * 128;

    float cacc[2][8][4];
    gemm_mma_tile(g_ao, wo, m0, n0, cacc, smem);

    int tid = threadIdx.x;
    int warp = tid >> 5, lane = tid & 31;
    int wm = warp & 3, wn = warp >> 2;
    int r0 = lane >> 2, c0 = (lane & 3) * 2;

#pragma unroll
    for (int mt = 0; mt < 2; mt++) {
#pragma unroll
        for (int ng = 0; ng < 8; ng++) {
            int col = n0 + wn * 64 + ng * 8 + c0;
#pragma unroll
            for (int half = 0; half < 2; half++) {
                int mg = m0 + wm * 32 + mt * 16 + r0 + half * 8;
                *(float2*)&out[(size_t)mg * HID + col] =
                    make_float2(cacc[mt][ng][2 * half], cacc[mt][ng][2 * half + 1]);
            }
        }
    }
}

// ---------------------------------------------------------------------------
// RoPE (in place). 64 threads = one row; thread d handles the (d, d+64) pair.
// ---------------------------------------------------------------------------
__device__ __forceinline__ void rope_row(float* base, int s)
{
    int d = threadIdx.x;                     // 0..63
    float inv = (float)exp2(-(double)d * 0.20762050593046747);  // log2(1e4)/64
    float ang = (float)s * inv;
    float sn, cs;
    sincosf(ang, &sn, &cs);
    float x1 = base[d], x2 = base[d + 64];
    base[d]      = x1 * cs - x2 * sn;
    base[d + 64] = x1 * sn + x2 * cs;
}

__global__ void rope_q() { rope_row(g_q + (size_t)blockIdx.x * HD, blockIdx.x & (S_LEN - 1)); }
__global__ void rope_k() { rope_row(g_k + (size_t)blockIdx.x * HD, blockIdx.x & (S_LEN - 1)); }

// ---------------------------------------------------------------------------
// Flash-style causal attention, fp32. BM=BN=64, 256 threads. (unchanged)
// ---------------------------------------------------------------------------
#define AQK 68
#define AVS 132
#define ATTN_SMEM_BYTES ((128 * AQK * 2 + 64 * AVS + 64 * AQK + 192) * 4)

__global__ void __launch_bounds__(256) attn_kernel(const float* __restrict__ kw)
{
    extern __shared__ float sm[];
    float* Qs = sm;
    float* Ks = Qs + 128 * AQK;
    float* Vs = Ks + 128 * AQK;
    float* Ps = Vs + 64 * AVS;
    float* mS = Ps + 64 * AQK;
    float* lS = mS + 64;
    float* aS = lS + 64;

    int tid = threadIdx.x;
    int ty = tid >> 4, tx = tid & 15;
    int mt = blockIdx.x, h = blockIdx.y, b = blockIdx.z;
    int m0 = mt * 64;
    int kh = h >> 2;
    float scale = kw[h] * 0.08838834764831845f;

    const float* qg = g_q + ((size_t)(b * NH  + h ) * S_LEN + m0) * HD;
    const float* kg = g_k + ((size_t)(b * NKV + kh) * S_LEN) * HD;
    const float* vg = g_v + ((size_t)(b * NKV + kh) * S_LEN) * HD;

    int lr = tid >> 2;
    int lc = (tid & 3) * 4;

    {
        const float* src = qg + (size_t)lr * HD;
#pragma unroll
        for (int q = 0; q < 8; q++) {
            int d = lc + q * 16;
            float4 v = *(const float4*)(src + d);
            Qs[(d + 0) * AQK + lr] = v.x * scale;
            Qs[(d + 1) * AQK + lr] = v.y * scale;
            Qs[(d + 2) * AQK + lr] = v.z * scale;
            Qs[(d + 3) * AQK + lr] = v.w * scale;
        }
    }
    if (tid < 64) { mS[tid] = -1e30f; lS[tid] = 0.f; }

    float o[4][8];
#pragma unroll
    for (int i = 0; i < 4; i++)
#pragma unroll
        for (int d = 0; d < 8; d++) o[i][d] = 0.f;

    for (int nt = 0; nt <= mt; nt++) {
        int n0 = nt * 64;
        __syncthreads();

        {
            const float* ks = kg + (size_t)(n0 + lr) * HD;
            const float* vs = vg + (size_t)(n0 + lr) * HD;
#pragma unroll
            for (int q = 0; q < 8; q++) {
                int d = lc + q * 16;
                float4 kv = *(const float4*)(ks + d);
                Ks[(d + 0) * AQK + lr] = kv.x;
                Ks[(d + 1) * AQK + lr] = kv.y;
                Ks[(d + 2) * AQK + lr] = kv.z;
                Ks[(d + 3) * AQK + lr] = kv.w;
                float4 vv = *(const float4*)(vs + d);
                *(float4*)&Vs[lr * AVS + d] = vv;
            }
        }
        __syncthreads();

        float sacc[4][4];
#pragma unroll
        for (int i = 0; i < 4; i++)
#pragma unroll
            for (int j = 0; j < 4; j++) sacc[i][j] = 0.f;

#pragma unroll 8
        for (int kk = 0; kk < HD; kk++) {
            float4 av = *(const float4*)&Qs[kk * AQK + ty * 4];
            float4 bv = *(const float4*)&Ks[kk * AQK + tx * 4];
            float a[4] = {av.x, av.y, av.z, av.w};
            float c[4] = {bv.x, bv.y, bv.z, bv.w};
#pragma unroll
            for (int i = 0; i < 4; i++)
#pragma unroll
                for (int j = 0; j < 4; j++)
                    sacc[i][j] = fmaf(a[i], c[j], sacc[i][j]);
        }

        if (nt == mt) {
#pragma unroll
            for (int i = 0; i < 4; i++)
#pragma unroll
                for (int j = 0; j < 4; j++)
                    if (n0 + tx * 4 + j > m0 + ty * 4 + i) sacc[i][j] = -1e30f;
        }
#pragma unroll
        for (int i = 0; i < 4; i++)
            *(float4*)&Ps[(ty * 4 + i) * AQK + tx * 4] =
                make_float4(sacc[i][0], sacc[i][1], sacc[i][2], sacc[i][3]);
        __syncthreads();

        if (tid < 64) {
            float* pr = &Ps[tid * AQK];
            float mold = mS[tid];
            float mx = mold;
#pragma unroll 8
            for (int j = 0; j < 64; j++) mx = fmaxf(mx, pr[j]);
            float alpha = __expf(mold - mx);
            float sum = 0.f;
#pragma unroll 8
            for (int j = 0; j < 64; j++) {
                float e = __expf(pr[j] - mx);
                pr[j] = e;
                sum += e;
            }
            mS[tid] = mx;
            lS[tid] = lS[tid] * alpha + sum;
            aS[tid] = alpha;
        }
        __syncthreads();

#pragma unroll
        for (int i = 0; i < 4; i++) {
            float al = aS[ty * 4 + i];
#pragma unroll
            for (int d = 0; d < 8; d++) o[i][d] *= al;
        }
#pragma unroll 2
        for (int j = 0; j < 64; j++) {
            float4 v0 = *(const float4*)&Vs[j * AVS + tx * 8];
            float4 v1 = *(const float4*)&Vs[j * AVS + tx * 8 + 4];
#pragma unroll
            for (int i = 0; i < 4; i++) {
                float p = Ps[(ty * 4 + i) * AQK + j];
                o[i][0] = fmaf(p, v0.x, o[i][0]);
                o[i][1] = fmaf(p, v0.y, o[i][1]);
                o[i][2] = fmaf(p, v0.z, o[i][2]);
                o[i][3] = fmaf(p, v0.w, o[i][3]);
                o[i][4] = fmaf(p, v1.x, o[i][4]);
                o[i][5] = fmaf(p, v1.y, o[i][5]);
                o[i][6] = fmaf(p, v1.z, o[i][6]);
                o[i][7] = fmaf(p, v1.w, o[i][7]);
            }
        }
    }

#pragma unroll
    for (int i = 0; i < 4; i++) {
        int r = ty * 4 + i;
        float inv = 1.0f / lS[r];
        float* dst = g_ao + ((size_t)(b * S_LEN + m0 + r)) * HID + h * HD + tx * 8;
        *(float4*)&dst[0] = make_float4(o[i][0] * inv, o[i][1] * inv,
                                        o[i][2] * inv, o[i][3] * inv);
        *(float4*)&dst[4] = make_float4(o[i][4] * inv, o[i][5] * inv,
                                        o[i][6] * inv, o[i][7] * inv);
    }
}

// ---------------------------------------------------------------------------
// Launch
// ---------------------------------------------------------------------------
extern "C" void kernel_launch(void* const* d_in, const int* in_sizes, int n_in,
                              void* d_out, int out_size)
{
    const float* x  = (const float*)d_in[0];
    const float* wq = (const float*)d_in[1];
    const float* wk = (const float*)d_in[2];
    const float* wv = (const float*)d_in[3];
    const float* wo = (const float*)d_in[4];
    const float* kw = (const float*)d_in[5];
    float* out = (float*)d_out;

    cudaFuncSetAttribute(attn_kernel, cudaFuncAttributeMaxDynamicSharedMemorySize,
                         ATTN_SMEM_BYTES);
    cudaFuncSetAttribute(gemm_qkv_mma, cudaFuncAttributeMaxDynamicSharedMemorySize,
                         GEMM_SMEM_MMA);
    cudaFuncSetAttribute(gemm_wo_mma, cudaFuncAttributeMaxDynamicSharedMemorySize,
                         GEMM_SMEM_MMA);

    // QKV projection: M=4096, N=3072 (24 N-tiles x 32 M-tiles)
    gemm_qkv_mma<<<dim3(24, 32), 256, GEMM_SMEM_MMA>>>(x, wq, wk, wv);

    // RoPE
    rope_q<<<BATCH * NH  * S_LEN, 64>>>();
    rope_k<<<BATCH * NKV * S_LEN, 64>>>();

    // Attention
    attn_kernel<<<dim3(S_LEN / 64, NH, BATCH), 256, ATTN_SMEM_BYTES>>>(kw);

    // Output projection: M=4096, N=2048 (16 x 32 tiles)
    gemm_wo_mma<<<dim3(16, 32), 256, GEMM_SMEM_MMA>>>(wo, out);
}

// round 5
// speedup vs baseline: 1.9725x; 1.4767x over previous
#include <cuda_runtime.h>
#include <cuda_bf16.h>
#include <math.h>
#include <cstdint>

#define S_LEN 2048
#define HID   2048
#define NH    16
#define NKV   4
#define HD    128
#define BATCH 2

// Scratch buffers (allocation-free rule: __device__ globals)
__device__ float g_q[(size_t)BATCH * NH  * S_LEN * HD];   // [b][h][s][d]
__device__ float g_k[(size_t)BATCH * NKV * S_LEN * HD];   // [b][kh][s][d]
__device__ float g_v[(size_t)BATCH * NKV * S_LEN * HD];   // [b][kh][s][d]
__device__ float g_ao[(size_t)BATCH * S_LEN * HID];       // [b][s][h*128+d]

// ===========================================================================
// Warp-level MMA helpers (baseline PTX: sm_80+ features)
// ===========================================================================
__device__ __forceinline__ uint32_t smem_u32(const void* p) {
    uint32_t a;
    asm("{ .reg .u64 t; cvta.to.shared.u64 t, %1; cvt.u32.u64 %0, t; }"
        : "=r"(a) : "l"(p));
    return a;
}
__device__ __forceinline__ void ldsm_x4(uint32_t r[4], uint32_t a) {
    asm volatile("ldmatrix.sync.aligned.m8n8.x4.shared.b16 {%0,%1,%2,%3}, [%4];"
                 : "=r"(r[0]), "=r"(r[1]), "=r"(r[2]), "=r"(r[3]) : "r"(a));
}
__device__ __forceinline__ void ldsm_x4_t(uint32_t r[4], uint32_t a) {
    asm volatile("ldmatrix.sync.aligned.m8n8.x4.trans.shared.b16 {%0,%1,%2,%3}, [%4];"
                 : "=r"(r[0]), "=r"(r[1]), "=r"(r[2]), "=r"(r[3]) : "r"(a));
}
__device__ __forceinline__ void mma16816(float c[4], const uint32_t a[4],
                                         uint32_t b0, uint32_t b1) {
    asm volatile("mma.sync.aligned.m16n8k16.row.col.f32.bf16.bf16.f32 "
                 "{%0,%1,%2,%3}, {%4,%5,%6,%7}, {%8,%9}, {%0,%1,%2,%3};"
                 : "+f"(c[0]), "+f"(c[1]), "+f"(c[2]), "+f"(c[3])
                 : "r"(a[0]), "r"(a[1]), "r"(a[2]), "r"(a[3]), "r"(b0), "r"(b1));
}

// Split fp32 pair -> (hi bf16x2, lo bf16x2); hi = rn(x), lo = rn(x - hi).
__device__ __forceinline__ void split2(float x0, float x1, uint32_t& hi, uint32_t& lo) {
    asm("cvt.rn.bf16x2.f32 %0, %1, %2;" : "=r"(hi) : "f"(x1), "f"(x0));
    float h0 = __uint_as_float(hi << 16);
    float h1 = __uint_as_float(hi & 0xFFFF0000u);
    float l0 = x0 - h0;
    float l1 = x1 - h1;
    asm("cvt.rn.bf16x2.f32 %0, %1, %2;" : "=r"(lo) : "f"(l1), "f"(l0));
}

#define SWZ(o) ((o) ^ (((o) >> 3) & 0x70))

// ===========================================================================
// Split-bf16 tensor-core GEMM (unchanged from R4, passes at 2.5e-5)
// ===========================================================================
#define BK 32
#define KCHUNKS (HID / BK)
#define TILE_BYTES 16384
#define STAGE_BYTES (2 * TILE_BYTES)
#define GEMM_SMEM_MMA (2 * STAGE_BYTES)

__device__ __forceinline__ void gemm_mma_tile(const float* __restrict__ A,
                                              const float* __restrict__ B,
                                              int m0, int n0,
                                              float cacc[2][8][4], char* smem)
{
    int tid = threadIdx.x;
    int warp = tid >> 5, lane = tid & 31;
    int wm = warp & 3, wn = warp >> 2;

    int lrow = tid >> 1;
    int lk   = (tid & 1) * 16;

    const float* ap = A + (size_t)(m0 + lrow) * HID + lk;
    const float* bp = B + (size_t)(n0 + lrow) * HID + lk;

    uint32_t sbase = smem_u32(smem);
    int lr16 = lane & 15;
    int lhalf = (lane >> 4) * 16;

    float4 ra[4], rb[4];

#pragma unroll
    for (int mt = 0; mt < 2; mt++)
#pragma unroll
        for (int ng = 0; ng < 8; ng++)
#pragma unroll
            for (int i = 0; i < 4; i++) cacc[mt][ng][i] = 0.f;

#pragma unroll
    for (int j = 0; j < 4; j++) {
        ra[j] = *(const float4*)(ap + j * 4);
        rb[j] = *(const float4*)(bp + j * 4);
    }

    auto store_stage = [&](int s) {
        char* ab = smem + s * STAGE_BYTES;
        char* bb = ab + TILE_BYTES;
#pragma unroll
        for (int j = 0; j < 4; j++) {
            uint32_t offh = (uint32_t)lrow * 128 + (lk + j * 4) * 2;
            uint32_t offl = offh + 64;
            uint32_t h0, l0, h1, l1;
            split2(ra[j].x, ra[j].y, h0, l0);
            split2(ra[j].z, ra[j].w, h1, l1);
            *(uint2*)(ab + SWZ(offh)) = make_uint2(h0, h1);
            *(uint2*)(ab + SWZ(offl)) = make_uint2(l0, l1);
            split2(rb[j].x, rb[j].y, h0, l0);
            split2(rb[j].z, rb[j].w, h1, l1);
            *(uint2*)(bb + SWZ(offh)) = make_uint2(h0, h1);
            *(uint2*)(bb + SWZ(offl)) = make_uint2(l0, l1);
        }
    };

    store_stage(0);
    __syncthreads();

    for (int c = 0; c < KCHUNKS; c++) {
        if (c + 1 < KCHUNKS) {
            const float* a2 = ap + (c + 1) * BK;
            const float* b2 = bp + (c + 1) * BK;
#pragma unroll
            for (int j = 0; j < 4; j++) {
                ra[j] = *(const float4*)(a2 + j * 4);
                rb[j] = *(const float4*)(b2 + j * 4);
            }
        }

        uint32_t abase = sbase + (c & 1) * STAGE_BYTES;
        uint32_t bbase = abase + TILE_BYTES;

#pragma unroll
        for (int seg = 0; seg < 3; seg++) {
            int sa = (seg == 1) ? 64 : 0;
            int sb = (seg == 2) ? 64 : 0;
#pragma unroll
            for (int kk = 0; kk < 2; kk++) {
                uint32_t af[2][4];
#pragma unroll
                for (int mt = 0; mt < 2; mt++) {
                    uint32_t off = (uint32_t)(wm * 32 + mt * 16 + lr16) * 128
                                   + sa + kk * 32 + lhalf;
                    ldsm_x4(af[mt], abase + SWZ(off));
                }
                uint32_t b0[8], b1[8];
#pragma unroll
                for (int t = 0; t < 4; t++) {
                    uint32_t off = (uint32_t)(wn * 64 + t * 16 + lr16) * 128
                                   + sb + kk * 32 + lhalf;
                    uint32_t r[4];
                    ldsm_x4(r, bbase + SWZ(off));
                    b0[2 * t] = r[0]; b0[2 * t + 1] = r[1];
                    b1[2 * t] = r[2]; b1[2 * t + 1] = r[3];
                }
#pragma unroll
                for (int mt = 0; mt < 2; mt++)
#pragma unroll
                    for (int ng = 0; ng < 8; ng++)
                        mma16816(cacc[mt][ng], af[mt], b0[ng], b1[ng]);
            }
        }

        if (c + 1 < KCHUNKS) store_stage((c + 1) & 1);
        __syncthreads();
    }
}

__global__ void __launch_bounds__(256, 1) gemm_qkv_mma(const float* __restrict__ x,
                                                       const float* __restrict__ wq,
                                                       const float* __restrict__ wk,
                                                       const float* __restrict__ wv)
{
    extern __shared__ char smem[];
    int nt = blockIdx.x;
    int m0 = blockIdx.y * 128;

    const float* B; float* dst_base; int h, nkvh;
    if (nt < 16)      { B = wq; h = nt;      dst_base = g_q; nkvh = NH;  }
    else if (nt < 20) { B = wk; h = nt - 16; dst_base = g_k; nkvh = NKV; }
    else              { B = wv; h = nt - 20; dst_base = g_v; nkvh = NKV; }

    float cacc[2][8][4];
    gemm_mma_tile(x, B, m0, h * HD, cacc, smem);

    int tid = threadIdx.x;
    int warp = tid >> 5, lane = tid & 31;
    int wm = warp & 3, wn = warp >> 2;
    int r0 = lane >> 2, c0 = (lane & 3) * 2;

#pragma unroll
    for (int mt = 0; mt < 2; mt++) {
#pragma unroll
        for (int ng = 0; ng < 8; ng++) {
            int col = wn * 64 + ng * 8 + c0;
#pragma unroll
            for (int half = 0; half < 2; half++) {
                int mg = m0 + wm * 32 + mt * 16 + r0 + half * 8;
                int b = mg >> 11, s = mg & (S_LEN - 1);
                float* d = dst_base + ((size_t)(b * nkvh + h) * S_LEN + s) * HD + col;
                *(float2*)d = make_float2(cacc[mt][ng][2 * half],
                                          cacc[mt][ng][2 * half + 1]);
            }
        }
    }
}

__global__ void __launch_bounds__(256, 1) gemm_wo_mma(const float* __restrict__ wo,
                                                      float* __restrict__ out)
{
    extern __shared__ char smem[];
    int n0 = blockIdx.x * 128;
    int m0 = blockIdx.y * 128;

    float cacc[2][8][4];
    gemm_mma_tile(g_ao, wo, m0, n0, cacc, smem);

    int tid = threadIdx.x;
    int warp = tid >> 5, lane = tid & 31;
    int wm = warp & 3, wn = warp >> 2;
    int r0 = lane >> 2, c0 = (lane & 3) * 2;

#pragma unroll
    for (int mt = 0; mt < 2; mt++) {
#pragma unroll
        for (int ng = 0; ng < 8; ng++) {
            int col = n0 + wn * 64 + ng * 8 + c0;
#pragma unroll
            for (int half = 0; half < 2; half++) {
                int mg = m0 + wm * 32 + mt * 16 + r0 + half * 8;
                *(float2*)&out[(size_t)mg * HID + col] =
                    make_float2(cacc[mt][ng][2 * half], cacc[mt][ng][2 * half + 1]);
            }
        }
    }
}

// ---------------------------------------------------------------------------
// RoPE (in place)
// ---------------------------------------------------------------------------
__device__ __forceinline__ void rope_row(float* base, int s)
{
    int d = threadIdx.x;
    float inv = (float)exp2(-(double)d * 0.20762050593046747);
    float ang = (float)s * inv;
    float sn, cs;
    sincosf(ang, &sn, &cs);
    float x1 = base[d], x2 = base[d + 64];
    base[d]      = x1 * cs - x2 * sn;
    base[d + 64] = x1 * sn + x2 * cs;
}
__global__ void rope_q() { rope_row(g_q + (size_t)blockIdx.x * HD, blockIdx.x & (S_LEN - 1)); }
__global__ void rope_k() { rope_row(g_k + (size_t)blockIdx.x * HD, blockIdx.x & (S_LEN - 1)); }

// ===========================================================================
// HMMA flash attention (split-bf16 both matmuls)
// BM=128 (8 warps x m16), BN=64 keys/tile. 256 threads.
// SMEM (bytes): QH[2][128][128] QL | KH[2][64][128] KL | VH[2][64][128] VL
// ===========================================================================
#define AT_QH 0
#define AT_QL 32768
#define AT_KH 65536
#define AT_KL 81920
#define AT_VH 98304
#define AT_VL 114688
#define ATTN_SMEM 131072

__global__ void __launch_bounds__(256, 1) attn_mma(const float* __restrict__ kw)
{
    extern __shared__ char smem[];
    uint32_t sb = smem_u32(smem);

    int tid = threadIdx.x;
    int wq = tid >> 5, lane = tid & 31;
    int lr16 = lane & 15;
    int lhalf = (lane >> 4) * 16;

    int mt = blockIdx.x, h = blockIdx.y, b = blockIdx.z;
    int m0 = mt * 128;
    int kh = h >> 2;
    float scale = kw[h] * 0.08838834764831845f;   // key_weight * 128^-0.5

    const float* qg = g_q + ((size_t)(b * NH  + h ) * S_LEN + m0) * HD;
    const float* kg = g_k + ((size_t)(b * NKV + kh) * S_LEN) * HD;
    const float* vg = g_v + ((size_t)(b * NKV + kh) * S_LEN) * HD;

    // ---- load + convert Q (scaled, split) ----
    {
        int row = tid >> 1;
        int dst = (tid & 1) * 64;
        const float* src = qg + (size_t)row * HD + dst;
        char* qh = smem + AT_QH + (dst >> 6) * 16384;
        char* ql = smem + AT_QL + (dst >> 6) * 16384;
#pragma unroll
        for (int j = 0; j < 16; j++) {
            float4 v = *(const float4*)(src + j * 4);
            v.x *= scale; v.y *= scale; v.z *= scale; v.w *= scale;
            uint32_t h0, l0, h1, l1;
            split2(v.x, v.y, h0, l0);
            split2(v.z, v.w, h1, l1);
            uint32_t off = (uint32_t)row * 128 + ((dst + j * 4) & 63) * 2;
            *(uint2*)(qh + SWZ(off)) = make_uint2(h0, h1);
            *(uint2*)(ql + SWZ(off)) = make_uint2(l0, l1);
        }
    }

    // running stats (replicated across the 4 lanes of each quad)
    float m1 = -1e30f, m2 = -1e30f, l1s = 0.f, l2s = 0.f;
    float oacc[16][4];
#pragma unroll
    for (int ng = 0; ng < 16; ng++)
#pragma unroll
        for (int i = 0; i < 4; i++) oacc[ng][i] = 0.f;

    // V trans-ldsm lane offsets
    int vrow_off = (lane & 7) + ((lane >> 3) & 1) * 8;
    int vcol8 = (lane >> 4) * 8;

    int ntiles = 2 * mt + 2;
    for (int nt = 0; nt < ntiles; nt++) {
        int n0 = nt * 64;
        __syncthreads();   // previous tile's MMAs done (and Q stores on first iter)

        // ---- load + convert K, V tiles ----
        {
            int row = tid >> 2;
            int dst = (tid & 3) * 32;
            int half = dst >> 6;
            const float* ks = kg + (size_t)(n0 + row) * HD + dst;
            const float* vs = vg + (size_t)(n0 + row) * HD + dst;
            char* kh_t = smem + AT_KH + half * 8192;
            char* kl_t = smem + AT_KL + half * 8192;
            char* vh_t = smem + AT_VH + half * 8192;
            char* vl_t = smem + AT_VL + half * 8192;
#pragma unroll
            for (int j = 0; j < 8; j++) {
                uint32_t off = SWZ((uint32_t)row * 128 + ((dst + j * 4) & 63) * 2);
                float4 v = *(const float4*)(ks + j * 4);
                uint32_t h0, l0, h1, l1;
                split2(v.x, v.y, h0, l0);
                split2(v.z, v.w, h1, l1);
                *(uint2*)(kh_t + off) = make_uint2(h0, h1);
                *(uint2*)(kl_t + off) = make_uint2(l0, l1);
                v = *(const float4*)(vs + j * 4);
                split2(v.x, v.y, h0, l0);
                split2(v.z, v.w, h1, l1);
                *(uint2*)(vh_t + off) = make_uint2(h0, h1);
                *(uint2*)(vl_t + off) = make_uint2(l0, l1);
            }
        }
        __syncthreads();

        // ---- S = Q K^T (split: QhKh + QlKh + QhKl) ----
        float sacc[8][4];
#pragma unroll
        for (int ng = 0; ng < 8; ng++)
#pragma unroll
            for (int i = 0; i < 4; i++) sacc[ng][i] = 0.f;

#pragma unroll
        for (int seg = 0; seg < 3; seg++) {
            uint32_t qbase = sb + ((seg == 1) ? AT_QL : AT_QH);
            uint32_t kbase = sb + ((seg == 2) ? AT_KL : AT_KH);
#pragma unroll
            for (int ks = 0; ks < 8; ks++) {
                int half = ks >> 2;
                uint32_t koff = (ks & 3) * 32 + lhalf;
                uint32_t af[4];
                ldsm_x4(af, qbase + half * 16384
                            + SWZ((uint32_t)(wq * 16 + lr16) * 128 + koff));
                uint32_t b0[8], b1[8];
#pragma unroll
                for (int t = 0; t < 4; t++) {
                    uint32_t r[4];
                    ldsm_x4(r, kbase + half * 8192
                               + SWZ((uint32_t)(t * 16 + lr16) * 128 + koff));
                    b0[2 * t] = r[0]; b0[2 * t + 1] = r[1];
                    b1[2 * t] = r[2]; b1[2 * t + 1] = r[3];
                }
#pragma unroll
                for (int ng = 0; ng < 8; ng++)
                    mma16816(sacc[ng], af, b0[ng], b1[ng]);
            }
        }

        // ---- causal mask (only the last two tiles can touch the diagonal) ----
        if (nt >= 2 * mt) {
            int rg1 = m0 + wq * 16 + (lane >> 2);
            int rg2 = rg1 + 8;
            int cb = n0 + (lane & 3) * 2;
#pragma unroll
            for (int ng = 0; ng < 8; ng++) {
                int c0g = cb + ng * 8;
                if (c0g > rg1)     sacc[ng][0] = -1e30f;
                if (c0g + 1 > rg1) sacc[ng][1] = -1e30f;
                if (c0g > rg2)     sacc[ng][2] = -1e30f;
                if (c0g + 1 > rg2) sacc[ng][3] = -1e30f;
            }
        }

        // ---- online softmax (in registers; quad shuffles for row reduce) ----
        float rmax1 = -1e30f, rmax2 = -1e30f;
#pragma unroll
        for (int ng = 0; ng < 8; ng++) {
            rmax1 = fmaxf(rmax1, fmaxf(sacc[ng][0], sacc[ng][1]));
            rmax2 = fmaxf(rmax2, fmaxf(sacc[ng][2], sacc[ng][3]));
        }
        rmax1 = fmaxf(rmax1, __shfl_xor_sync(0xffffffffu, rmax1, 1));
        rmax1 = fmaxf(rmax1, __shfl_xor_sync(0xffffffffu, rmax1, 2));
        rmax2 = fmaxf(rmax2, __shfl_xor_sync(0xffffffffu, rmax2, 1));
        rmax2 = fmaxf(rmax2, __shfl_xor_sync(0xffffffffu, rmax2, 2));

        float mn1 = fmaxf(m1, rmax1);
        float mn2 = fmaxf(m2, rmax2);
        float alpha1 = __expf(m1 - mn1);
        float alpha2 = __expf(m2 - mn2);
        m1 = mn1; m2 = mn2;

        float rsum1 = 0.f, rsum2 = 0.f;
#pragma unroll
        for (int ng = 0; ng < 8; ng++) {
            sacc[ng][0] = __expf(sacc[ng][0] - mn1);
            sacc[ng][1] = __expf(sacc[ng][1] - mn1);
            sacc[ng][2] = __expf(sacc[ng][2] - mn2);
            sacc[ng][3] = __expf(sacc[ng][3] - mn2);
            rsum1 += sacc[ng][0] + sacc[ng][1];
            rsum2 += sacc[ng][2] + sacc[ng][3];
        }
        rsum1 += __shfl_xor_sync(0xffffffffu, rsum1, 1);
        rsum1 += __shfl_xor_sync(0xffffffffu, rsum1, 2);
        rsum2 += __shfl_xor_sync(0xffffffffu, rsum2, 1);
        rsum2 += __shfl_xor_sync(0xffffffffu, rsum2, 2);
        l1s = l1s * alpha1 + rsum1;
        l2s = l2s * alpha2 + rsum2;

        // rescale running O
#pragma unroll
        for (int ng = 0; ng < 16; ng++) {
            oacc[ng][0] *= alpha1; oacc[ng][1] *= alpha1;
            oacc[ng][2] *= alpha2; oacc[ng][3] *= alpha2;
        }

        // ---- O += P V (split: PhVh + PlVh + PhVl); P frags from registers ----
#pragma unroll
        for (int ks = 0; ks < 4; ks++) {
            uint32_t pha[4], pla[4];
            split2(sacc[2 * ks][0],     sacc[2 * ks][1],     pha[0], pla[0]);
            split2(sacc[2 * ks][2],     sacc[2 * ks][3],     pha[1], pla[1]);
            split2(sacc[2 * ks + 1][0], sacc[2 * ks + 1][1], pha[2], pla[2]);
            split2(sacc[2 * ks + 1][2], sacc[2 * ks + 1][3], pha[3], pla[3]);

            uint32_t vrow = (uint32_t)(ks * 16 + vrow_off) * 128;
#pragma unroll
            for (int t = 0; t < 8; t++) {
                int half = t >> 2;
                uint32_t coff = ((t & 3) * 16 + vcol8) * 2;
                uint32_t r[4];
                ldsm_x4_t(r, sb + AT_VH + half * 8192 + SWZ(vrow + coff));
                mma16816(oacc[2 * t],     pha, r[0], r[1]);
                mma16816(oacc[2 * t + 1], pha, r[2], r[3]);
                mma16816(oacc[2 * t],     pla, r[0], r[1]);
                mma16816(oacc[2 * t + 1], pla, r[2], r[3]);
            }
#pragma unroll
            for (int t = 0; t < 8; t++) {
                int half = t >> 2;
                uint32_t coff = ((t & 3) * 16 + vcol8) * 2;
                uint32_t r[4];
                ldsm_x4_t(r, sb + AT_VL + half * 8192 + SWZ(vrow + coff));
                mma16816(oacc[2 * t],     pha, r[0], r[1]);
                mma16816(oacc[2 * t + 1], pha, r[2], r[3]);
            }
        }
    }

    // ---- epilogue: normalize, write to g_ao [b][s][h*128+d] ----
    float inv1 = 1.0f / l1s;
    float inv2 = 1.0f / l2s;
    int r1 = m0 + wq * 16 + (lane >> 2);
    int c0 = (lane & 3) * 2;
    float* dst1 = g_ao + ((size_t)(b * S_LEN + r1)) * HID + h * HD;
    float* dst2 = g_ao + ((size_t)(b * S_LEN + r1 + 8)) * HID + h * HD;
#pragma unroll
    for (int ng = 0; ng < 16; ng++) {
        int d = ng * 8 + c0;
        *(float2*)(dst1 + d) = make_float2(oacc[ng][0] * inv1, oacc[ng][1] * inv1);
        *(float2*)(dst2 + d) = make_float2(oacc[ng][2] * inv2, oacc[ng][3] * inv2);
    }
}

// ---------------------------------------------------------------------------
// Launch
// ---------------------------------------------------------------------------
extern "C" void kernel_launch(void* const* d_in, const int* in_sizes, int n_in,
                              void* d_out, int out_size)
{
    const float* x  = (const float*)d_in[0];
    const float* wq = (const float*)d_in[1];
    const float* wk = (const float*)d_in[2];
    const float* wv = (const float*)d_in[3];
    const float* wo = (const float*)d_in[4];
    const float* kw = (const float*)d_in[5];
    float* out = (float*)d_out;

    cudaFuncSetAttribute(attn_mma, cudaFuncAttributeMaxDynamicSharedMemorySize,
                         ATTN_SMEM);
    cudaFuncSetAttribute(gemm_qkv_mma, cudaFuncAttributeMaxDynamicSharedMemorySize,
                         GEMM_SMEM_MMA);
    cudaFuncSetAttribute(gemm_wo_mma, cudaFuncAttributeMaxDynamicSharedMemorySize,
                         GEMM_SMEM_MMA);

    // QKV projection: M=4096, N=3072
    gemm_qkv_mma<<<dim3(24, 32), 256, GEMM_SMEM_MMA>>>(x, wq, wk, wv);

    // RoPE
    rope_q<<<BATCH * NH  * S_LEN, 64>>>();
    rope_k<<<BATCH * NKV * S_LEN, 64>>>();

    // Attention (BM=128)
    attn_mma<<<dim3(S_LEN / 128, NH, BATCH), 256, ATTN_SMEM>>>(kw);

    // Output projection: M=4096, N=2048
    gemm_wo_mma<<<dim3(16, 32), 256, GEMM_SMEM_MMA>>>(wo, out);
}